// round 15
// baseline (speedup 1.0000x reference)
#include <cuda_runtime.h>
#include <math.h>

#define NE 480000
#define NN 30000

// ---------------- scratch (device globals; no allocation) ----------------
static __device__ float4 g_geo[NE];          // ux,uy,uz,r
static __device__ float  g_radial[NE*8];
static __device__ float  g_dradial[NE*8];    // d(radial)/dr
static __device__ float  g_h00[NN*16];
static __device__ float  g_h01[NN*16];
static __device__ float  g_h11[NN*48];
static __device__ float  g_h21[NN*80];
static __device__ float  g_g0f[NN*16];
static __device__ float  g_ga01[NN*16];
static __device__ float  g_ga00[NN*16];
static __device__ float  g_ga10[NN*48];
static __device__ float  g_ga20[NN*80];
static __device__ double g_energy;
// ---- CSR: [0,NN)=cntR [NN,2NN)=cntC [2NN,3NN)=curR [3NN,4NN)=curC
static __device__ int    g_icsr[4*NN];
static __device__ int    g_offR[NN], g_offC[NN];
static __device__ int    g_lstR[NE], g_lstC[NE];
static __device__ float  g_gv[NE*3];         // per-edge dE/d(edge_vec), fp32

__device__ __forceinline__ void sh_basis_f(float ux, float uy, float uz,
                                           float* s1, float* s2) {
    const float SQ3 = 1.7320508075688772f;
    const float S15 = 3.872983346207417f;
    const float S5  = 2.23606797749979f;
    s1[0] = SQ3 * ux; s1[1] = SQ3 * uy; s1[2] = SQ3 * uz;
    s2[0] = S15 * ux * uy;
    s2[1] = S15 * uy * uz;
    s2[2] = 0.5f * S5 * (3.f * uz * uz - 1.f);
    s2[3] = S15 * ux * uz;
    s2[4] = 0.5f * S15 * (ux * ux - uy * uy);
}

// Convergent (post-loop / uniform-grid) width-16 broadcast.
#define SHFL16(v, src) __shfl_sync(0xffffffffu, (v), (src), 16)

// ---------------- forward: geometry (+ dradial + CSR counting) ----------------
__global__ void k_geom_fwd(const float* __restrict__ pos, const int* __restrict__ ei) {
    int e = blockIdx.x * blockDim.x + threadIdx.x;
    if (e >= NE) return;
    int rw = ei[e], cl = ei[NE + e];
    float vx = pos[3*rw+0] - pos[3*cl+0];
    float vy = pos[3*rw+1] - pos[3*cl+1];
    float vz = pos[3*rw+2] - pos[3*cl+2];
    float r = sqrtf(vx*vx + vy*vy + vz*vz + 1e-12f);
    float inv = 1.f / r;
    g_geo[e] = make_float4(vx*inv, vy*inv, vz*inv, r);
    const float A = 0.6324555320336759f;       // sqrt(2/5)
    const float KPI = 0.6283185307179586f;     // pi/5
    #pragma unroll
    for (int n = 0; n < 8; n++) {
        float kn = (float)(n + 1) * KPI;
        float sn, cn;
        sincosf(kn * r, &sn, &cn);
        float rad = A * sn * inv;
        g_radial[e*8 + n]  = rad;
        g_dradial[e*8 + n] = (A * kn * cn - rad) * inv;
    }
    atomicAdd(&g_icsr[rw], 1);
    atomicAdd(&g_icsr[NN + cl], 1);
}

// ---------------- CSR: exclusive scans for both R and C in one launch ----------------
__global__ void k_scan2() {
    __shared__ int part[1024];
    const int CH = 32;
    int t = threadIdx.x;
    int base = t * CH;
    for (int pass = 0; pass < 2; pass++) {
        const int* cnt = pass ? (g_icsr + NN) : g_icsr;
        int*       off = pass ? g_offC : g_offR;
        int s = 0;
        for (int i = 0; i < CH; i++) {
            int idx = base + i;
            if (idx < NN) s += cnt[idx];
        }
        part[t] = s;
        __syncthreads();
        for (int o = 1; o < 1024; o <<= 1) {
            int v = (t >= o) ? part[t - o] : 0;
            __syncthreads();
            part[t] += v;
            __syncthreads();
        }
        int run = (t > 0) ? part[t - 1] : 0;
        for (int i = 0; i < CH; i++) {
            int idx = base + i;
            if (idx < NN) { off[idx] = run; run += cnt[idx]; }
        }
        __syncthreads();
    }
}

// ---------------- CSR: fill (unordered) ----------------
__global__ void k_fill(const int* __restrict__ ei) {
    int e = blockIdx.x * blockDim.x + threadIdx.x;
    if (e >= NE) return;
    int rw = ei[e], cl = ei[NE + e];
    int p1 = g_offR[rw] + atomicAdd(&g_icsr[2*NN + rw], 1);
    g_lstR[p1] = e;
    int p2 = g_offC[cl] + atomicAdd(&g_icsr[3*NN + cl], 1);
    g_lstC[p2] = e;
}

// ---------------- CSR: sort buckets ascending (R and C split across threads) ----
__global__ void k_sort2() {
    int t = blockIdx.x * blockDim.x + threadIdx.x;
    if (t >= 2 * NN) return;
    int n = (t < NN) ? t : t - NN;
    int* lst = (t < NN) ? g_lstR : g_lstC;
    int lo  = (t < NN) ? g_offR[n] : g_offC[n];
    int hi  = lo + ((t < NN) ? g_icsr[n] : g_icsr[NN + n]);
    for (int i = lo + 1; i < hi; i++) {
        int key = lst[i], j = i - 1;
        while (j >= lo && lst[j] > key) { lst[j+1] = lst[j]; j--; }
        lst[j+1] = key;
    }
}

// ---------------- forward: h0 init = emb[z] @ W_init ----------------
__global__ void k_node_init(const float* __restrict__ emb, const int* __restrict__ z,
                            const float* __restrict__ W_init) {
    __shared__ float Ws[256];
    for (int i = threadIdx.x; i < 256; i += blockDim.x) Ws[i] = W_init[i];
    __syncthreads();
    int t = blockIdx.x * blockDim.x + threadIdx.x;
    if (t >= NN * 16) return;
    int n = t >> 4, d = t & 15;
    const float* er = emb + z[n] * 16;
    float acc = 0.f;
    #pragma unroll
    for (int k = 0; k < 16; k++) acc += er[k] * Ws[k*16 + d];
    g_h00[t] = acc;
}

// ---------------- forward: block0 gather + fused node update ----------------
__global__ void k_gath_fwd0(const int* __restrict__ ei,
                            const float* __restrict__ Wr, const float* __restrict__ br,
                            const float* __restrict__ Wout) {
    __shared__ float Wrs[640], brs[80], W0s[256], W1s[256], W2s[256];
    for (int i = threadIdx.x; i < 640; i += blockDim.x) Wrs[i] = Wr[i];
    for (int i = threadIdx.x; i < 80;  i += blockDim.x) brs[i] = br[i];
    for (int i = threadIdx.x; i < 256; i += blockDim.x) {
        W0s[i] = Wout[i]; W1s[i] = Wout[256 + i]; W2s[i] = Wout[512 + i];
    }
    __syncthreads();
    int t = blockIdx.x * blockDim.x + threadIdx.x;
    int n = t >> 4, c = t & 15;
    float w0b = brs[c], w1b = brs[16 + c], w2b = brs[32 + c];
    float acc0 = 0.f, a1[3] = {0,0,0}, a2[5] = {0,0,0,0,0};
    int lo = g_offR[n], hi = lo + g_icsr[n];
    for (int i = lo; i < hi; i++) {
        int e = g_lstR[i];
        int cl = ei[NE + e];
        float4 g = g_geo[e];
        float s1[3], s2[5];
        sh_basis_f(g.x, g.y, g.z, s1, s2);
        float4 r0 = *reinterpret_cast<const float4*>(g_radial + e*8);
        float4 r1 = *reinterpret_cast<const float4*>(g_radial + e*8 + 4);
        float rad[8] = {r0.x, r0.y, r0.z, r0.w, r1.x, r1.y, r1.z, r1.w};
        float w0 = w0b, w1 = w1b, w2 = w2b;
        #pragma unroll
        for (int k = 0; k < 8; k++) {
            w0 += rad[k] * Wrs[k*80 + c];
            w1 += rad[k] * Wrs[k*80 + 16 + c];
            w2 += rad[k] * Wrs[k*80 + 32 + c];
        }
        float h0c = g_h00[cl*16 + c];
        acc0 += w0 * h0c;
        float f1 = w1 * h0c, f2 = w2 * h0c;
        #pragma unroll
        for (int m = 0; m < 3; m++) a1[m] += f1 * s1[m];
        #pragma unroll
        for (int m = 0; m < 5; m++) a2[m] += f2 * s2[m];
    }
    // fused node update (convergent): lane c plays output channel d=c
    float h01v = g_h00[n*16 + c];
    float h11v[3] = {0,0,0}, h21v[5] = {0,0,0,0,0};
    #pragma unroll
    for (int cc = 0; cc < 16; cc++) {
        float b0 = SHFL16(acc0, cc);
        h01v += b0 * W0s[cc*16 + c];
        float w1 = W1s[cc*16 + c];
        #pragma unroll
        for (int m = 0; m < 3; m++) h11v[m] += SHFL16(a1[m], cc) * w1;
        float w2 = W2s[cc*16 + c];
        #pragma unroll
        for (int m = 0; m < 5; m++) h21v[m] += SHFL16(a2[m], cc) * w2;
    }
    g_h01[n*16 + c] = h01v;
    #pragma unroll
    for (int m = 0; m < 3; m++) g_h11[n*48 + c*3 + m] = h11v[m];
    #pragma unroll
    for (int m = 0; m < 5; m++) g_h21[n*80 + c*5 + m] = h21v[m];
}

// ---------------- forward: block1 gather + fused readout + bwd_node1 ----------------
__global__ void k_fwd1_readout(const int* __restrict__ ei,
                               const float* __restrict__ Wr, const float* __restrict__ br,
                               const float* __restrict__ W10, const float* __restrict__ W_read,
                               const float* __restrict__ W1, const float* __restrict__ b1,
                               const float* __restrict__ W2, const float* __restrict__ b2) {
    __shared__ float Wrs[640], brs[80], W10s[256], WRs[256], W1s[256], W2s[16], b1s[16];
    __shared__ float b2s;
    __shared__ double esum[16];
    for (int i = threadIdx.x; i < 640; i += blockDim.x) Wrs[i] = Wr[i];
    for (int i = threadIdx.x; i < 80;  i += blockDim.x) brs[i] = br[i];
    for (int i = threadIdx.x; i < 256; i += blockDim.x) {
        W10s[i] = W10[i]; WRs[i] = W_read[i]; W1s[i] = W1[i];
    }
    if (threadIdx.x < 16) { W2s[threadIdx.x] = W2[threadIdx.x]; b1s[threadIdx.x] = b1[threadIdx.x]; }
    if (threadIdx.x == 0) b2s = b2[0];
    __syncthreads();
    int t = blockIdx.x * blockDim.x + threadIdx.x;
    int n = t >> 4, c = t & 15;
    float w0b = brs[c], w3b = brs[48 + c], w4b = brs[64 + c];
    float acc = 0.f;                       // a01[n,c]
    int lo = g_offR[n], hi = lo + g_icsr[n];
    for (int i = lo; i < hi; i++) {
        int e = g_lstR[i];
        int cl = ei[NE + e];
        float4 g = g_geo[e];
        float s1[3], s2[5];
        sh_basis_f(g.x, g.y, g.z, s1, s2);
        float4 r0 = *reinterpret_cast<const float4*>(g_radial + e*8);
        float4 r1 = *reinterpret_cast<const float4*>(g_radial + e*8 + 4);
        float rad[8] = {r0.x, r0.y, r0.z, r0.w, r1.x, r1.y, r1.z, r1.w};
        float w0 = w0b, w3 = w3b, w4 = w4b;
        #pragma unroll
        for (int k = 0; k < 8; k++) {
            w0 += rad[k] * Wrs[k*80 + c];
            w3 += rad[k] * Wrs[k*80 + 48 + c];
            w4 += rad[k] * Wrs[k*80 + 64 + c];
        }
        float h0c = g_h01[cl*16 + c];
        float d1 = 0.f, d2 = 0.f;
        #pragma unroll
        for (int m = 0; m < 3; m++) d1 += g_h11[cl*48 + c*3 + m] * s1[m];
        #pragma unroll
        for (int m = 0; m < 5; m++) d2 += g_h21[cl*80 + c*5 + m] * s2[m];
        acc += w0 * h0c + w3 * d1 + w4 * d2;
    }
    // distributed readout (convergent; lane c == channel index)
    float h0f = g_h01[n*16 + c];
    #pragma unroll
    for (int cc = 0; cc < 16; cc++) h0f += SHFL16(acc, cc) * W10s[cc*16 + c];
    float invv = 0.f;
    #pragma unroll
    for (int cc = 0; cc < 16; cc++) invv += SHFL16(h0f, cc) * WRs[cc*16 + c];
    float tt = b1s[c];
    #pragma unroll
    for (int d = 0; d < 16; d++) tt += SHFL16(invv, d) * W1s[d*16 + c];
    float sg = 1.f / (1.f + expf(-tt));
    float sl = tt * sg * W2s[c];
    float sp = sg * (1.f + tt * (1.f - sg)) * W2s[c];
    float q = 0.f;
    #pragma unroll
    for (int k = 0; k < 16; k++) q += SHFL16(sp, k) * W1s[c*16 + k];
    float g0f = 0.f;
    #pragma unroll
    for (int d = 0; d < 16; d++) g0f += SHFL16(q, d) * WRs[c*16 + d];
    g_g0f[n*16 + c] = g0f;
    float ga = 0.f;
    #pragma unroll
    for (int d = 0; d < 16; d++) ga += SHFL16(g0f, d) * W10s[c*16 + d];
    g_ga01[n*16 + c] = ga;
    // energy
    #pragma unroll
    for (int off = 8; off > 0; off >>= 1) sl += __shfl_xor_sync(0xffffffffu, sl, off, 16);
    int grp = threadIdx.x >> 4;
    if (c == 0) esum[grp] = (double)(sl + b2s);
    __syncthreads();
    if (threadIdx.x == 0) {
        double s = 0.0;
        #pragma unroll
        for (int i = 0; i < 16; i++) s += esum[i];
        atomicAdd(&g_energy, s);
    }
}

// ---------------- backward: block1 col-gather + bwd_node0 + block1 gv ----------------
__global__ void k_gath_bwd1(const int* __restrict__ ei,
                            const float* __restrict__ Wr, const float* __restrict__ br,
                            const float* __restrict__ Wout) {
    __shared__ float Wrs[640], brs[80], W0s[256], W1s[256], W2s[256];
    for (int i = threadIdx.x; i < 640; i += blockDim.x) Wrs[i] = Wr[i];
    for (int i = threadIdx.x; i < 80;  i += blockDim.x) brs[i] = br[i];
    for (int i = threadIdx.x; i < 256; i += blockDim.x) {
        W0s[i] = Wout[i]; W1s[i] = Wout[256 + i]; W2s[i] = Wout[512 + i];
    }
    __syncthreads();
    int t = blockIdx.x * blockDim.x + threadIdx.x;
    int n = t >> 4, c = t & 15;
    unsigned gmask = 0xFFFFu << (threadIdx.x & 16);   // halves diverge in trip count
    float w0b = brs[c], w3b = brs[48 + c], w4b = brs[64 + c];
    // own-node forward activations (cl == n), registers
    float h0c = g_h01[n*16 + c];
    float h1c[3], h2c[5];
    #pragma unroll
    for (int m = 0; m < 3; m++) h1c[m] = g_h11[n*48 + c*3 + m];
    #pragma unroll
    for (int m = 0; m < 5; m++) h2c[m] = g_h21[n*80 + c*5 + m];
    float g01acc = g_g0f[n*16 + c];           // identity path
    float g11acc[3] = {0,0,0}, g21acc[5] = {0,0,0,0,0};
    const float SQ3 = 1.7320508075688772f;
    const float S15 = 3.872983346207417f;
    const float S5  = 2.23606797749979f;
    int lo = g_offC[n], hi = lo + g_icsr[NN + n];
    for (int i = lo; i < hi; i++) {
        int e = g_lstC[i];
        int rw = ei[e];
        float4 g = g_geo[e];
        float s1[3], s2[5];
        sh_basis_f(g.x, g.y, g.z, s1, s2);
        float4 r0 = *reinterpret_cast<const float4*>(g_radial + e*8);
        float4 r1 = *reinterpret_cast<const float4*>(g_radial + e*8 + 4);
        float rad[8] = {r0.x, r0.y, r0.z, r0.w, r1.x, r1.y, r1.z, r1.w};
        float4 q0 = *reinterpret_cast<const float4*>(g_dradial + e*8);
        float4 q1 = *reinterpret_cast<const float4*>(g_dradial + e*8 + 4);
        float dco[8] = {q0.x, q0.y, q0.z, q0.w, q1.x, q1.y, q1.z, q1.w};
        float w0 = w0b, w3 = w3b, w4 = w4b;
        float Dw0 = 0.f, Dw3 = 0.f, Dw4 = 0.f;
        #pragma unroll
        for (int k = 0; k < 8; k++) {
            float rr = rad[k], dd = dco[k];
            w0  += rr * Wrs[k*80 + c];
            w3  += rr * Wrs[k*80 + 48 + c];
            w4  += rr * Wrs[k*80 + 64 + c];
            Dw0 += dd * Wrs[k*80 + c];
            Dw3 += dd * Wrs[k*80 + 48 + c];
            Dw4 += dd * Wrs[k*80 + 64 + c];
        }
        float gm0 = g_ga01[rw*16 + c];
        g01acc += gm0 * w0;
        float gw3 = gm0 * w3, gw4 = gm0 * w4;
        #pragma unroll
        for (int m = 0; m < 3; m++) g11acc[m] += gw3 * s1[m];
        #pragma unroll
        for (int m = 0; m < 5; m++) g21acc[m] += gw4 * s2[m];
        // block1 gv partial (per lane; gv linear in gs, gd)
        float d1 = 0.f, d2 = 0.f;
        #pragma unroll
        for (int m = 0; m < 3; m++) d1 += h1c[m] * s1[m];
        #pragma unroll
        for (int m = 0; m < 5; m++) d2 += h2c[m] * s2[m];
        float grp = (gm0 * h0c) * Dw0 + (gm0 * d1) * Dw3 + (gm0 * d2) * Dw4;
        float p1x = gw3 * h1c[0], p1y = gw3 * h1c[1], p1z = gw3 * h1c[2];
        float p20 = gw4 * h2c[0], p21 = gw4 * h2c[1], p22 = gw4 * h2c[2];
        float p23 = gw4 * h2c[3], p24 = gw4 * h2c[4];
        float ux = g.x, uy = g.y, uz = g.z, invr = 1.f / g.w;
        float gux = SQ3 * p1x + S15 * (uy * p20 + uz * p23 + ux * p24);
        float guy = SQ3 * p1y + S15 * (ux * p20 + uz * p21 - uy * p24);
        float guz = SQ3 * p1z + S15 * (uy * p21 + ux * p23) + 3.f * S5 * uz * p22;
        float guu = gux * ux + guy * uy + guz * uz;
        float gvx = grp * ux + (gux - guu * ux) * invr;
        float gvy = grp * uy + (guy - guu * uy) * invr;
        float gvz = grp * uz + (guz - guu * uz) * invr;
        #pragma unroll
        for (int off = 8; off > 0; off >>= 1) {
            gvx += __shfl_xor_sync(gmask, gvx, off, 16);
            gvy += __shfl_xor_sync(gmask, gvy, off, 16);
            gvz += __shfl_xor_sync(gmask, gvz, off, 16);
        }
        if (c == 0) {
            g_gv[e*3 + 0] = gvx;
            g_gv[e*3 + 1] = gvy;
            g_gv[e*3 + 2] = gvz;
        }
    }
    // fused bwd_node0 (convergent; lane c == output channel)
    float ga00 = 0.f, ga10[3] = {0,0,0}, ga20[5] = {0,0,0,0,0};
    #pragma unroll
    for (int d = 0; d < 16; d++) {
        ga00 += SHFL16(g01acc, d) * W0s[c*16 + d];
        float w1 = W1s[c*16 + d];
        #pragma unroll
        for (int m = 0; m < 3; m++) ga10[m] += SHFL16(g11acc[m], d) * w1;
        float w2 = W2s[c*16 + d];
        #pragma unroll
        for (int m = 0; m < 5; m++) ga20[m] += SHFL16(g21acc[m], d) * w2;
    }
    g_ga00[n*16 + c] = ga00;
    #pragma unroll
    for (int m = 0; m < 3; m++) g_ga10[n*48 + c*3 + m] = ga10[m];
    #pragma unroll
    for (int m = 0; m < 5; m++) g_ga20[n*80 + c*5 + m] = ga20[m];
}

// ---------------- backward: block0 row-gather gv accumulation ----------------
__global__ void k_bwd0_gv(const int* __restrict__ ei,
                          const float* __restrict__ Wr, const float* __restrict__ br) {
    __shared__ float Wrs[640], brs[80];
    for (int i = threadIdx.x; i < 640; i += blockDim.x) Wrs[i] = Wr[i];
    for (int i = threadIdx.x; i < 80;  i += blockDim.x) brs[i] = br[i];
    __syncthreads();
    int t = blockIdx.x * blockDim.x + threadIdx.x;
    int n = t >> 4, c = t & 15;        // n plays rw
    unsigned gmask = 0xFFFFu << (threadIdx.x & 16);
    float w1b = brs[16 + c], w2b = brs[32 + c];
    // hoist block0 cotangents for this node (registers)
    float gm0 = g_ga00[n*16 + c];
    float gm1[3], gm2[5];
    #pragma unroll
    for (int m = 0; m < 3; m++) gm1[m] = g_ga10[n*48 + c*3 + m];
    #pragma unroll
    for (int m = 0; m < 5; m++) gm2[m] = g_ga20[n*80 + c*5 + m];
    const float SQ3 = 1.7320508075688772f;
    const float S15 = 3.872983346207417f;
    const float S5  = 2.23606797749979f;
    int lo = g_offR[n], hi = lo + g_icsr[n];
    for (int i = lo; i < hi; i++) {
        int e = g_lstR[i];
        int cl = ei[NE + e];
        float4 g = g_geo[e];
        float s1[3], s2[5];
        sh_basis_f(g.x, g.y, g.z, s1, s2);
        float4 r0 = *reinterpret_cast<const float4*>(g_radial + e*8);
        float4 r1 = *reinterpret_cast<const float4*>(g_radial + e*8 + 4);
        float rad[8] = {r0.x, r0.y, r0.z, r0.w, r1.x, r1.y, r1.z, r1.w};
        float4 q0 = *reinterpret_cast<const float4*>(g_dradial + e*8);
        float4 q1 = *reinterpret_cast<const float4*>(g_dradial + e*8 + 4);
        float dco[8] = {q0.x, q0.y, q0.z, q0.w, q1.x, q1.y, q1.z, q1.w};
        float w1 = w1b, w2 = w2b;
        float Dw0 = 0.f, Dw1 = 0.f, Dw2 = 0.f;
        #pragma unroll
        for (int k = 0; k < 8; k++) {
            float rr = rad[k], dd = dco[k];
            w1  += rr * Wrs[k*80 + 16 + c];
            w2  += rr * Wrs[k*80 + 32 + c];
            Dw0 += dd * Wrs[k*80 + c];
            Dw1 += dd * Wrs[k*80 + 16 + c];
            Dw2 += dd * Wrs[k*80 + 32 + c];
        }
        float h0c = g_h00[cl*16 + c];
        float d1 = 0.f, d2 = 0.f;
        #pragma unroll
        for (int m = 0; m < 3; m++) d1 += gm1[m] * s1[m];
        #pragma unroll
        for (int m = 0; m < 5; m++) d2 += gm2[m] * s2[m];
        float grp = (gm0 * h0c) * Dw0 + (h0c * d1) * Dw1 + (h0c * d2) * Dw2;
        float w1h = w1 * h0c, w2h = w2 * h0c;
        float p1x = gm1[0] * w1h, p1y = gm1[1] * w1h, p1z = gm1[2] * w1h;
        float p20 = gm2[0] * w2h, p21 = gm2[1] * w2h, p22 = gm2[2] * w2h;
        float p23 = gm2[3] * w2h, p24 = gm2[4] * w2h;
        float ux = g.x, uy = g.y, uz = g.z, invr = 1.f / g.w;
        float gux = SQ3 * p1x + S15 * (uy * p20 + uz * p23 + ux * p24);
        float guy = SQ3 * p1y + S15 * (ux * p20 + uz * p21 - uy * p24);
        float guz = SQ3 * p1z + S15 * (uy * p21 + ux * p23) + 3.f * S5 * uz * p22;
        float guu = gux * ux + guy * uy + guz * uz;
        float gvx = grp * ux + (gux - guu * ux) * invr;
        float gvy = grp * uy + (guy - guu * uy) * invr;
        float gvz = grp * uz + (guz - guu * uz) * invr;
        #pragma unroll
        for (int off = 8; off > 0; off >>= 1) {
            gvx += __shfl_xor_sync(gmask, gvx, off, 16);
            gvy += __shfl_xor_sync(gmask, gvy, off, 16);
            gvz += __shfl_xor_sync(gmask, gvz, off, 16);
        }
        if (c == 0) {
            g_gv[e*3 + 0] += gvx;   // each edge in exactly one row bucket: no race
            g_gv[e*3 + 1] += gvy;
            g_gv[e*3 + 2] += gvz;
        }
    }
}

// ---------------- forces: 8 lanes/node, sums bit-identical to XLA order ----------------
__global__ void k_forces(float* __restrict__ out) {
    int t = blockIdx.x * blockDim.x + threadIdx.x;
    if (t >= NN * 8) return;
    int n = t >> 3, l = t & 7;
    if (t == 0) out[0] = (float)g_energy;
    float acc = 0.f;
    if (l < 3) {
        int lo = g_offR[n], hi = lo + g_icsr[n];
        for (int i = lo; i < hi; i++) acc += g_gv[g_lstR[i]*3 + l];
    } else if (l < 7 && l >= 4) {
        int m = l - 4;
        int lo = g_offC[n], hi = lo + g_icsr[NN + n];
        for (int i = lo; i < hi; i++) acc += -g_gv[g_lstC[i]*3 + m];
    }
    float partner = __shfl_down_sync(0xffffffffu, acc, 4, 8);
    if (l < 3) out[1 + n*3 + l] = -(acc + partner);
}

// ---------------- host ----------------
extern "C" void kernel_launch(void* const* d_in, const int* in_sizes, int n_in,
                              void* d_out, int out_size) {
    const float* pos    = (const float*)d_in[0];
    const int*   z      = (const int*)  d_in[1];
    const int*   ei     = (const int*)  d_in[2];
    const float* emb    = (const float*)d_in[3];
    const float* W_init = (const float*)d_in[4];
    const float* Wr     = (const float*)d_in[5];
    const float* br     = (const float*)d_in[6];
    const float* W_out  = (const float*)d_in[7];
    const float* W_read = (const float*)d_in[8];
    const float* W1     = (const float*)d_in[9];
    const float* b1     = (const float*)d_in[10];
    const float* W2     = (const float*)d_in[11];
    const float* b2     = (const float*)d_in[12];
    float* out = (float*)d_out;

    void *pen, *picsr;
    cudaGetSymbolAddress(&pen,   g_energy);
    cudaGetSymbolAddress(&picsr, g_icsr);

    cudaMemsetAsync(pen,   0, sizeof(double), 0);
    cudaMemsetAsync(picsr, 0, sizeof(int) * 4 * NN, 0);

    const int TPB = 256;
    k_geom_fwd    <<<NE / TPB, TPB>>>(pos, ei);
    k_scan2       <<<1, 1024>>>();
    k_fill        <<<NE / TPB, TPB>>>(ei);
    k_sort2       <<<(2 * NN + TPB - 1) / TPB, TPB>>>();
    k_node_init   <<<NN * 16 / TPB, TPB>>>(emb, z, W_init);
    k_gath_fwd0   <<<NN * 16 / TPB, TPB>>>(ei, Wr, br, W_out);
    k_fwd1_readout<<<NN * 16 / TPB, TPB>>>(ei, Wr + 640, br + 80,
                                           W_out + 768, W_read, W1, b1, W2, b2);
    k_gath_bwd1   <<<NN * 16 / TPB, TPB>>>(ei, Wr + 640, br + 80, W_out);
    k_bwd0_gv     <<<NN * 16 / TPB, TPB>>>(ei, Wr, br);
    k_forces      <<<(NN * 8 + TPB - 1) / TPB, TPB>>>(out);
}

// round 16
// speedup vs baseline: 1.6007x; 1.6007x over previous
#include <cuda_runtime.h>
#include <math.h>

#define NE 480000
#define NN 30000

// ---------------- scratch (device globals; no allocation) ----------------
static __device__ float4 g_geo[NE];          // ux,uy,uz,r
static __device__ float  g_radial[NE*8];
static __device__ float  g_dradial[NE*8];    // d(radial)/dr
static __device__ float  g_h00[NN*16];
static __device__ float  g_h01[NN*16];
static __device__ float  g_h11[NN*48];
static __device__ float  g_h21[NN*80];
static __device__ float  g_g0f[NN*16];
static __device__ float  g_ga01[NN*16];
static __device__ float  g_ga00[NN*16];
static __device__ float  g_ga10[NN*48];
static __device__ float  g_ga20[NN*80];
static __device__ double g_energy;
// ---- CSR: [0,NN)=cntR [NN,2NN)=cntC [2NN,3NN)=curR [3NN,4NN)=curC
static __device__ int    g_icsr[4*NN];
static __device__ int    g_offR[NN], g_offC[NN];
static __device__ int    g_lstR[NE], g_lstC[NE];
static __device__ float  g_gv[NE*3];         // per-edge dE/d(edge_vec), fp32

__device__ __forceinline__ void sh_basis_f(float ux, float uy, float uz,
                                           float* s1, float* s2) {
    const float SQ3 = 1.7320508075688772f;
    const float S15 = 3.872983346207417f;
    const float S5  = 2.23606797749979f;
    s1[0] = SQ3 * ux; s1[1] = SQ3 * uy; s1[2] = SQ3 * uz;
    s2[0] = S15 * ux * uy;
    s2[1] = S15 * uy * uz;
    s2[2] = 0.5f * S5 * (3.f * uz * uz - 1.f);
    s2[3] = S15 * ux * uz;
    s2[4] = 0.5f * S15 * (ux * ux - uy * uy);
}

// Convergent (post-loop / uniform-grid) width-16 broadcast.
#define SHFL16(v, src) __shfl_sync(0xffffffffu, (v), (src), 16)

// ---------------- forward: geometry (+ dradial + CSR counting) ----------------
__global__ void k_geom_fwd(const float* __restrict__ pos, const int* __restrict__ ei) {
    int e = blockIdx.x * blockDim.x + threadIdx.x;
    if (e >= NE) return;
    int rw = ei[e], cl = ei[NE + e];
    float vx = pos[3*rw+0] - pos[3*cl+0];
    float vy = pos[3*rw+1] - pos[3*cl+1];
    float vz = pos[3*rw+2] - pos[3*cl+2];
    float r = sqrtf(vx*vx + vy*vy + vz*vz + 1e-12f);
    float inv = 1.f / r;
    g_geo[e] = make_float4(vx*inv, vy*inv, vz*inv, r);
    const float A = 0.6324555320336759f;       // sqrt(2/5)
    const float KPI = 0.6283185307179586f;     // pi/5
    #pragma unroll
    for (int n = 0; n < 8; n++) {
        float kn = (float)(n + 1) * KPI;
        float sn, cn;
        sincosf(kn * r, &sn, &cn);
        float rad = A * sn * inv;
        g_radial[e*8 + n]  = rad;
        g_dradial[e*8 + n] = (A * kn * cn - rad) * inv;
    }
    atomicAdd(&g_icsr[rw], 1);
    atomicAdd(&g_icsr[NN + cl], 1);
}

// ---------------- CSR: exclusive scans for both R and C in one launch ----------------
__global__ void k_scan2() {
    __shared__ int part[1024];
    const int CH = 32;
    int t = threadIdx.x;
    int base = t * CH;
    for (int pass = 0; pass < 2; pass++) {
        const int* cnt = pass ? (g_icsr + NN) : g_icsr;
        int*       off = pass ? g_offC : g_offR;
        int s = 0;
        for (int i = 0; i < CH; i++) {
            int idx = base + i;
            if (idx < NN) s += cnt[idx];
        }
        part[t] = s;
        __syncthreads();
        for (int o = 1; o < 1024; o <<= 1) {
            int v = (t >= o) ? part[t - o] : 0;
            __syncthreads();
            part[t] += v;
            __syncthreads();
        }
        int run = (t > 0) ? part[t - 1] : 0;
        for (int i = 0; i < CH; i++) {
            int idx = base + i;
            if (idx < NN) { off[idx] = run; run += cnt[idx]; }
        }
        __syncthreads();
    }
}

// ---------------- CSR: fill (unordered) ----------------
__global__ void k_fill(const int* __restrict__ ei) {
    int e = blockIdx.x * blockDim.x + threadIdx.x;
    if (e >= NE) return;
    int rw = ei[e], cl = ei[NE + e];
    int p1 = g_offR[rw] + atomicAdd(&g_icsr[2*NN + rw], 1);
    g_lstR[p1] = e;
    int p2 = g_offC[cl] + atomicAdd(&g_icsr[3*NN + cl], 1);
    g_lstC[p2] = e;
}

// ---------------- CSR: sort buckets ascending (R and C split across threads) ----
__global__ void k_sort2() {
    int t = blockIdx.x * blockDim.x + threadIdx.x;
    if (t >= 2 * NN) return;
    int n = (t < NN) ? t : t - NN;
    int* lst = (t < NN) ? g_lstR : g_lstC;
    int lo  = (t < NN) ? g_offR[n] : g_offC[n];
    int hi  = lo + ((t < NN) ? g_icsr[n] : g_icsr[NN + n]);
    for (int i = lo + 1; i < hi; i++) {
        int key = lst[i], j = i - 1;
        while (j >= lo && lst[j] > key) { lst[j+1] = lst[j]; j--; }
        lst[j+1] = key;
    }
}

// ---------------- forward: h0 init = emb[z] @ W_init ----------------
__global__ void k_node_init(const float* __restrict__ emb, const int* __restrict__ z,
                            const float* __restrict__ W_init) {
    __shared__ float Ws[256];
    for (int i = threadIdx.x; i < 256; i += blockDim.x) Ws[i] = W_init[i];
    __syncthreads();
    int t = blockIdx.x * blockDim.x + threadIdx.x;
    if (t >= NN * 16) return;
    int n = t >> 4, d = t & 15;
    const float* er = emb + z[n] * 16;
    float acc = 0.f;
    #pragma unroll
    for (int k = 0; k < 16; k++) acc += er[k] * Ws[k*16 + d];
    g_h00[t] = acc;
}

// ---------------- forward: block0 gather + fused node update ----------------
__global__ void k_gath_fwd0(const int* __restrict__ ei,
                            const float* __restrict__ Wr, const float* __restrict__ br,
                            const float* __restrict__ Wout) {
    __shared__ float Wrs[640], brs[80], W0s[256], W1s[256], W2s[256];
    for (int i = threadIdx.x; i < 640; i += blockDim.x) Wrs[i] = Wr[i];
    for (int i = threadIdx.x; i < 80;  i += blockDim.x) brs[i] = br[i];
    for (int i = threadIdx.x; i < 256; i += blockDim.x) {
        W0s[i] = Wout[i]; W1s[i] = Wout[256 + i]; W2s[i] = Wout[512 + i];
    }
    __syncthreads();
    int t = blockIdx.x * blockDim.x + threadIdx.x;
    int n = t >> 4, c = t & 15;
    float w0b = brs[c], w1b = brs[16 + c], w2b = brs[32 + c];
    float acc0 = 0.f, a1[3] = {0,0,0}, a2[5] = {0,0,0,0,0};
    int lo = g_offR[n], hi = lo + g_icsr[n];
    for (int i = lo; i < hi; i++) {
        int e = g_lstR[i];
        int cl = ei[NE + e];
        float4 g = g_geo[e];
        float s1[3], s2[5];
        sh_basis_f(g.x, g.y, g.z, s1, s2);
        float4 r0 = *reinterpret_cast<const float4*>(g_radial + e*8);
        float4 r1 = *reinterpret_cast<const float4*>(g_radial + e*8 + 4);
        float rad[8] = {r0.x, r0.y, r0.z, r0.w, r1.x, r1.y, r1.z, r1.w};
        float w0 = w0b, w1 = w1b, w2 = w2b;
        #pragma unroll
        for (int k = 0; k < 8; k++) {
            w0 += rad[k] * Wrs[k*80 + c];
            w1 += rad[k] * Wrs[k*80 + 16 + c];
            w2 += rad[k] * Wrs[k*80 + 32 + c];
        }
        float h0c = g_h00[cl*16 + c];
        acc0 += w0 * h0c;
        float f1 = w1 * h0c, f2 = w2 * h0c;
        #pragma unroll
        for (int m = 0; m < 3; m++) a1[m] += f1 * s1[m];
        #pragma unroll
        for (int m = 0; m < 5; m++) a2[m] += f2 * s2[m];
    }
    // fused node update (convergent): lane c plays output channel d=c
    float h01v = g_h00[n*16 + c];
    float h11v[3] = {0,0,0}, h21v[5] = {0,0,0,0,0};
    #pragma unroll
    for (int cc = 0; cc < 16; cc++) {
        float b0 = SHFL16(acc0, cc);
        h01v += b0 * W0s[cc*16 + c];
        float w1 = W1s[cc*16 + c];
        #pragma unroll
        for (int m = 0; m < 3; m++) h11v[m] += SHFL16(a1[m], cc) * w1;
        float w2 = W2s[cc*16 + c];
        #pragma unroll
        for (int m = 0; m < 5; m++) h21v[m] += SHFL16(a2[m], cc) * w2;
    }
    g_h01[n*16 + c] = h01v;
    #pragma unroll
    for (int m = 0; m < 3; m++) g_h11[n*48 + c*3 + m] = h11v[m];
    #pragma unroll
    for (int m = 0; m < 5; m++) g_h21[n*80 + c*5 + m] = h21v[m];
}

// ---------------- forward: block1 gather + fused readout + bwd_node1 ----------------
__global__ void k_fwd1_readout(const int* __restrict__ ei,
                               const float* __restrict__ Wr, const float* __restrict__ br,
                               const float* __restrict__ W10, const float* __restrict__ W_read,
                               const float* __restrict__ W1, const float* __restrict__ b1,
                               const float* __restrict__ W2, const float* __restrict__ b2) {
    __shared__ float Wrs[640], brs[80], W10s[256], WRs[256], W1s[256], W2s[16], b1s[16];
    __shared__ float b2s;
    __shared__ double esum[16];
    for (int i = threadIdx.x; i < 640; i += blockDim.x) Wrs[i] = Wr[i];
    for (int i = threadIdx.x; i < 80;  i += blockDim.x) brs[i] = br[i];
    for (int i = threadIdx.x; i < 256; i += blockDim.x) {
        W10s[i] = W10[i]; WRs[i] = W_read[i]; W1s[i] = W1[i];
    }
    if (threadIdx.x < 16) { W2s[threadIdx.x] = W2[threadIdx.x]; b1s[threadIdx.x] = b1[threadIdx.x]; }
    if (threadIdx.x == 0) b2s = b2[0];
    __syncthreads();
    int t = blockIdx.x * blockDim.x + threadIdx.x;
    int n = t >> 4, c = t & 15;
    float w0b = brs[c], w3b = brs[48 + c], w4b = brs[64 + c];
    float acc = 0.f;                       // a01[n,c]
    int lo = g_offR[n], hi = lo + g_icsr[n];
    for (int i = lo; i < hi; i++) {
        int e = g_lstR[i];
        int cl = ei[NE + e];
        float4 g = g_geo[e];
        float s1[3], s2[5];
        sh_basis_f(g.x, g.y, g.z, s1, s2);
        float4 r0 = *reinterpret_cast<const float4*>(g_radial + e*8);
        float4 r1 = *reinterpret_cast<const float4*>(g_radial + e*8 + 4);
        float rad[8] = {r0.x, r0.y, r0.z, r0.w, r1.x, r1.y, r1.z, r1.w};
        float w0 = w0b, w3 = w3b, w4 = w4b;
        #pragma unroll
        for (int k = 0; k < 8; k++) {
            w0 += rad[k] * Wrs[k*80 + c];
            w3 += rad[k] * Wrs[k*80 + 48 + c];
            w4 += rad[k] * Wrs[k*80 + 64 + c];
        }
        float h0c = g_h01[cl*16 + c];
        float d1 = 0.f, d2 = 0.f;
        #pragma unroll
        for (int m = 0; m < 3; m++) d1 += g_h11[cl*48 + c*3 + m] * s1[m];
        #pragma unroll
        for (int m = 0; m < 5; m++) d2 += g_h21[cl*80 + c*5 + m] * s2[m];
        acc += w0 * h0c + w3 * d1 + w4 * d2;
    }
    // distributed readout (convergent; lane c == channel index)
    float h0f = g_h01[n*16 + c];
    #pragma unroll
    for (int cc = 0; cc < 16; cc++) h0f += SHFL16(acc, cc) * W10s[cc*16 + c];
    float invv = 0.f;
    #pragma unroll
    for (int cc = 0; cc < 16; cc++) invv += SHFL16(h0f, cc) * WRs[cc*16 + c];
    float tt = b1s[c];
    #pragma unroll
    for (int d = 0; d < 16; d++) tt += SHFL16(invv, d) * W1s[d*16 + c];
    float sg = 1.f / (1.f + expf(-tt));
    float sl = tt * sg * W2s[c];
    float sp = sg * (1.f + tt * (1.f - sg)) * W2s[c];
    float q = 0.f;
    #pragma unroll
    for (int k = 0; k < 16; k++) q += SHFL16(sp, k) * W1s[c*16 + k];
    float g0f = 0.f;
    #pragma unroll
    for (int d = 0; d < 16; d++) g0f += SHFL16(q, d) * WRs[c*16 + d];
    g_g0f[n*16 + c] = g0f;
    float ga = 0.f;
    #pragma unroll
    for (int d = 0; d < 16; d++) ga += SHFL16(g0f, d) * W10s[c*16 + d];
    g_ga01[n*16 + c] = ga;
    // energy
    #pragma unroll
    for (int off = 8; off > 0; off >>= 1) sl += __shfl_xor_sync(0xffffffffu, sl, off, 16);
    int grp = threadIdx.x >> 4;
    if (c == 0) esum[grp] = (double)(sl + b2s);
    __syncthreads();
    if (threadIdx.x == 0) {
        double s = 0.0;
        #pragma unroll
        for (int i = 0; i < 16; i++) s += esum[i];
        atomicAdd(&g_energy, s);
    }
}

// ---------------- backward: block1 slim gather + fused bwd_node0 ----------------
__global__ void k_gath_bwd1(const int* __restrict__ ei,
                            const float* __restrict__ Wr, const float* __restrict__ br,
                            const float* __restrict__ Wout) {
    __shared__ float Wrs[640], brs[80], W0s[256], W1s[256], W2s[256];
    for (int i = threadIdx.x; i < 640; i += blockDim.x) Wrs[i] = Wr[i];
    for (int i = threadIdx.x; i < 80;  i += blockDim.x) brs[i] = br[i];
    for (int i = threadIdx.x; i < 256; i += blockDim.x) {
        W0s[i] = Wout[i]; W1s[i] = Wout[256 + i]; W2s[i] = Wout[512 + i];
    }
    __syncthreads();
    int t = blockIdx.x * blockDim.x + threadIdx.x;
    int n = t >> 4, c = t & 15;
    float w0b = brs[c], w3b = brs[48 + c], w4b = brs[64 + c];
    float g01acc = g_g0f[n*16 + c];           // identity path
    float g11acc[3] = {0,0,0}, g21acc[5] = {0,0,0,0,0};
    int lo = g_offC[n], hi = lo + g_icsr[NN + n];
    for (int i = lo; i < hi; i++) {
        int e = g_lstC[i];
        int rw = ei[e];
        float4 g = g_geo[e];
        float s1[3], s2[5];
        sh_basis_f(g.x, g.y, g.z, s1, s2);
        float4 r0 = *reinterpret_cast<const float4*>(g_radial + e*8);
        float4 r1 = *reinterpret_cast<const float4*>(g_radial + e*8 + 4);
        float rad[8] = {r0.x, r0.y, r0.z, r0.w, r1.x, r1.y, r1.z, r1.w};
        float w0 = w0b, w3 = w3b, w4 = w4b;
        #pragma unroll
        for (int k = 0; k < 8; k++) {
            w0 += rad[k] * Wrs[k*80 + c];
            w3 += rad[k] * Wrs[k*80 + 48 + c];
            w4 += rad[k] * Wrs[k*80 + 64 + c];
        }
        float gm0 = g_ga01[rw*16 + c];
        g01acc += gm0 * w0;
        float gw3 = gm0 * w3, gw4 = gm0 * w4;
        #pragma unroll
        for (int m = 0; m < 3; m++) g11acc[m] += gw3 * s1[m];
        #pragma unroll
        for (int m = 0; m < 5; m++) g21acc[m] += gw4 * s2[m];
    }
    // fused bwd_node0 (convergent; lane c == output channel)
    float ga00 = 0.f, ga10[3] = {0,0,0}, ga20[5] = {0,0,0,0,0};
    #pragma unroll
    for (int d = 0; d < 16; d++) {
        ga00 += SHFL16(g01acc, d) * W0s[c*16 + d];
        float w1 = W1s[c*16 + d];
        #pragma unroll
        for (int m = 0; m < 3; m++) ga10[m] += SHFL16(g11acc[m], d) * w1;
        float w2 = W2s[c*16 + d];
        #pragma unroll
        for (int m = 0; m < 5; m++) ga20[m] += SHFL16(g21acc[m], d) * w2;
    }
    g_ga00[n*16 + c] = ga00;
    #pragma unroll
    for (int m = 0; m < 3; m++) g_ga10[n*48 + c*3 + m] = ga10[m];
    #pragma unroll
    for (int m = 0; m < 5; m++) g_ga20[n*80 + c*5 + m] = ga20[m];
}

// ---------------- backward: BOTH blocks, per-lane gv partials, 3-value butterfly ----
__global__ void k_bwd_edge_all(const int* __restrict__ ei,
                               const float* __restrict__ Wr, const float* __restrict__ br) {
    // Wr layout: block0 at [0,640), block1 at [640,1280); br: [0,80) and [80,160)
    __shared__ float Wrs[1280], brs[160];
    for (int i = threadIdx.x; i < 1280; i += blockDim.x) Wrs[i] = Wr[i];
    for (int i = threadIdx.x; i < 160;  i += blockDim.x) brs[i] = br[i];
    __syncthreads();
    long t = (long)blockIdx.x * blockDim.x + threadIdx.x;
    int e = (int)(t >> 4), c = (int)(t & 15);
    int rw = ei[e], cl = ei[NE + e];
    float4 g = g_geo[e];
    float s1[3], s2[5];
    sh_basis_f(g.x, g.y, g.z, s1, s2);
    float4 r0 = *reinterpret_cast<const float4*>(g_radial + e*8);
    float4 r1 = *reinterpret_cast<const float4*>(g_radial + e*8 + 4);
    float rad[8] = {r0.x, r0.y, r0.z, r0.w, r1.x, r1.y, r1.z, r1.w};
    float4 d0 = *reinterpret_cast<const float4*>(g_dradial + e*8);
    float4 dd1 = *reinterpret_cast<const float4*>(g_dradial + e*8 + 4);
    float dco[8] = {d0.x, d0.y, d0.z, d0.w, dd1.x, dd1.y, dd1.z, dd1.w};

    float b0w1 = brs[16 + c], b0w2 = brs[32 + c];
    float b1w3 = brs[128 + c], b1w4 = brs[144 + c];
    float D0w0 = 0.f, D0w1 = 0.f, D0w2 = 0.f, D1w0 = 0.f, D1w3 = 0.f, D1w4 = 0.f;
    #pragma unroll
    for (int n = 0; n < 8; n++) {
        float rr = rad[n], dd = dco[n];
        b0w1 += rr * Wrs[n*80 + 16 + c];
        b0w2 += rr * Wrs[n*80 + 32 + c];
        b1w3 += rr * Wrs[640 + n*80 + 48 + c];
        b1w4 += rr * Wrs[640 + n*80 + 64 + c];
        D0w0 += dd * Wrs[n*80 + c];
        D0w1 += dd * Wrs[n*80 + 16 + c];
        D0w2 += dd * Wrs[n*80 + 32 + c];
        D1w0 += dd * Wrs[640 + n*80 + c];
        D1w3 += dd * Wrs[640 + n*80 + 48 + c];
        D1w4 += dd * Wrs[640 + n*80 + 64 + c];
    }

    float g1[3], g2[5], grp;
    {
        float gm0 = g_ga01[rw*16 + c];
        float h0c = g_h01[cl*16 + c];
        float h1c[3], h2c[5];
        #pragma unroll
        for (int m = 0; m < 3; m++) h1c[m] = g_h11[cl*48 + c*3 + m];
        #pragma unroll
        for (int m = 0; m < 5; m++) h2c[m] = g_h21[cl*80 + c*5 + m];
        float gw3 = gm0 * b1w3, gw4 = gm0 * b1w4;
        #pragma unroll
        for (int m = 0; m < 3; m++) g1[m] = gw3 * h1c[m];
        #pragma unroll
        for (int m = 0; m < 5; m++) g2[m] = gw4 * h2c[m];
        float d1 = 0.f, d2 = 0.f;
        #pragma unroll
        for (int m = 0; m < 3; m++) d1 += h1c[m] * s1[m];
        #pragma unroll
        for (int m = 0; m < 5; m++) d2 += h2c[m] * s2[m];
        grp = (gm0 * h0c) * D1w0 + (gm0 * d1) * D1w3 + (gm0 * d2) * D1w4;
    }
    {
        float gm0 = g_ga00[rw*16 + c];
        float gm1[3], gm2[5];
        #pragma unroll
        for (int m = 0; m < 3; m++) gm1[m] = g_ga10[rw*48 + c*3 + m];
        #pragma unroll
        for (int m = 0; m < 5; m++) gm2[m] = g_ga20[rw*80 + c*5 + m];
        float h0c = g_h00[cl*16 + c];
        float d1 = 0.f, d2 = 0.f;
        #pragma unroll
        for (int m = 0; m < 3; m++) d1 += gm1[m] * s1[m];
        #pragma unroll
        for (int m = 0; m < 5; m++) d2 += gm2[m] * s2[m];
        float w1h = b0w1 * h0c, w2h = b0w2 * h0c;
        #pragma unroll
        for (int m = 0; m < 3; m++) g1[m] += gm1[m] * w1h;
        #pragma unroll
        for (int m = 0; m < 5; m++) g2[m] += gm2[m] * w2h;
        grp += (gm0 * h0c) * D0w0 + (h0c * d1) * D0w1 + (h0c * d2) * D0w2;
    }

    float ux = g.x, uy = g.y, uz = g.z, invr = 1.f / g.w;
    const float SQ3 = 1.7320508075688772f;
    const float S15 = 3.872983346207417f;
    const float S5  = 2.23606797749979f;
    float gux = SQ3 * g1[0] + S15 * (uy * g2[0] + uz * g2[3] + ux * g2[4]);
    float guy = SQ3 * g1[1] + S15 * (ux * g2[0] + uz * g2[1] - uy * g2[4]);
    float guz = SQ3 * g1[2] + S15 * (uy * g2[1] + ux * g2[3]) + 3.f * S5 * uz * g2[2];
    float guu = gux * ux + guy * uy + guz * uz;
    float gvx = grp * ux + (gux - guu * ux) * invr;
    float gvy = grp * uy + (guy - guu * uy) * invr;
    float gvz = grp * uz + (guz - guu * uz) * invr;

    #pragma unroll
    for (int off = 8; off > 0; off >>= 1) {
        gvx += __shfl_xor_sync(0xffffffffu, gvx, off, 16);
        gvy += __shfl_xor_sync(0xffffffffu, gvy, off, 16);
        gvz += __shfl_xor_sync(0xffffffffu, gvz, off, 16);
    }
    if (c == 0) {
        g_gv[e*3 + 0] = gvx;
        g_gv[e*3 + 1] = gvy;
        g_gv[e*3 + 2] = gvz;
    }
}

// ---------------- forces: 8 lanes/node, sums bit-identical to XLA order ----------------
__global__ void k_forces(float* __restrict__ out) {
    int t = blockIdx.x * blockDim.x + threadIdx.x;
    if (t >= NN * 8) return;
    int n = t >> 3, l = t & 7;
    if (t == 0) out[0] = (float)g_energy;
    float acc = 0.f;
    if (l < 3) {
        int lo = g_offR[n], hi = lo + g_icsr[n];
        for (int i = lo; i < hi; i++) acc += g_gv[g_lstR[i]*3 + l];
    } else if (l < 7 && l >= 4) {
        int m = l - 4;
        int lo = g_offC[n], hi = lo + g_icsr[NN + n];
        for (int i = lo; i < hi; i++) acc += -g_gv[g_lstC[i]*3 + m];
    }
    float partner = __shfl_down_sync(0xffffffffu, acc, 4, 8);
    if (l < 3) out[1 + n*3 + l] = -(acc + partner);
}

// ---------------- host ----------------
extern "C" void kernel_launch(void* const* d_in, const int* in_sizes, int n_in,
                              void* d_out, int out_size) {
    const float* pos    = (const float*)d_in[0];
    const int*   z      = (const int*)  d_in[1];
    const int*   ei     = (const int*)  d_in[2];
    const float* emb    = (const float*)d_in[3];
    const float* W_init = (const float*)d_in[4];
    const float* Wr     = (const float*)d_in[5];
    const float* br     = (const float*)d_in[6];
    const float* W_out  = (const float*)d_in[7];
    const float* W_read = (const float*)d_in[8];
    const float* W1     = (const float*)d_in[9];
    const float* b1     = (const float*)d_in[10];
    const float* W2     = (const float*)d_in[11];
    const float* b2     = (const float*)d_in[12];
    float* out = (float*)d_out;

    void *pen, *picsr;
    cudaGetSymbolAddress(&pen,   g_energy);
    cudaGetSymbolAddress(&picsr, g_icsr);

    cudaMemsetAsync(pen,   0, sizeof(double), 0);
    cudaMemsetAsync(picsr, 0, sizeof(int) * 4 * NN, 0);

    const int TPB = 256;
    k_geom_fwd    <<<NE / TPB, TPB>>>(pos, ei);
    k_scan2       <<<1, 1024>>>();
    k_fill        <<<NE / TPB, TPB>>>(ei);
    k_sort2       <<<(2 * NN + TPB - 1) / TPB, TPB>>>();
    k_node_init   <<<NN * 16 / TPB, TPB>>>(emb, z, W_init);
    k_gath_fwd0   <<<NN * 16 / TPB, TPB>>>(ei, Wr, br, W_out);
    k_fwd1_readout<<<NN * 16 / TPB, TPB>>>(ei, Wr + 640, br + 80,
                                           W_out + 768, W_read, W1, b1, W2, b2);
    k_gath_bwd1   <<<NN * 16 / TPB, TPB>>>(ei, Wr + 640, br + 80, W_out);
    k_bwd_edge_all<<<NE * 16 / TPB, TPB>>>(ei, Wr, br);
    k_forces      <<<(NN * 8 + TPB - 1) / TPB, TPB>>>(out);
}

// round 17
// speedup vs baseline: 1.6718x; 1.0445x over previous
#include <cuda_runtime.h>
#include <math.h>

#define NE 480000
#define NN 30000

// ---------------- scratch (device globals; no allocation) ----------------
static __device__ float4 g_geo[NE];          // ux,uy,uz,r
static __device__ float  g_radial[NE*8];
static __device__ float  g_dradial[NE*8];    // d(radial)/dr
static __device__ float  g_h00[NN*16];
static __device__ float  g_h01[NN*16];
static __device__ float  g_h11[NN*48];
static __device__ float  g_h21[NN*80];
static __device__ float  g_g0f[NN*16];
static __device__ float  g_ga01[NN*16];
static __device__ float  g_ga00[NN*16];
static __device__ float  g_ga10[NN*48];
static __device__ float  g_ga20[NN*80];
static __device__ double g_energy;
// ---- CSR: [0,NN)=cntR [NN,2NN)=cntC [2NN,3NN)=curR [3NN,4NN)=curC
static __device__ int    g_icsr[4*NN];
static __device__ int    g_offR[NN], g_offC[NN];
static __device__ int    g_lstR[NE], g_lstC[NE];
static __device__ float  g_gv[NE*3];         // per-edge dE/d(edge_vec), fp32

__device__ __forceinline__ void sh_basis_f(float ux, float uy, float uz,
                                           float* s1, float* s2) {
    const float SQ3 = 1.7320508075688772f;
    const float S15 = 3.872983346207417f;
    const float S5  = 2.23606797749979f;
    s1[0] = SQ3 * ux; s1[1] = SQ3 * uy; s1[2] = SQ3 * uz;
    s2[0] = S15 * ux * uy;
    s2[1] = S15 * uy * uz;
    s2[2] = 0.5f * S5 * (3.f * uz * uz - 1.f);
    s2[3] = S15 * ux * uz;
    s2[4] = 0.5f * S15 * (ux * ux - uy * uy);
}

// Convergent (post-loop / uniform-grid) width-16 broadcast.
#define SHFL16(v, src) __shfl_sync(0xffffffffu, (v), (src), 16)

// ---------------- forward: geometry (+ dradial + CSR counting) ----------------
__global__ void k_geom_fwd(const float* __restrict__ pos, const int* __restrict__ ei) {
    int e = blockIdx.x * blockDim.x + threadIdx.x;
    if (e >= NE) return;
    int rw = ei[e], cl = ei[NE + e];
    float vx = pos[3*rw+0] - pos[3*cl+0];
    float vy = pos[3*rw+1] - pos[3*cl+1];
    float vz = pos[3*rw+2] - pos[3*cl+2];
    float r = sqrtf(vx*vx + vy*vy + vz*vz + 1e-12f);
    float inv = 1.f / r;
    g_geo[e] = make_float4(vx*inv, vy*inv, vz*inv, r);
    const float A = 0.6324555320336759f;       // sqrt(2/5)
    const float KPI = 0.6283185307179586f;     // pi/5
    // Chebyshev recurrence: sin/cos of harmonics from one sincosf
    float x = KPI * r;
    float s1v, c1v;
    sincosf(x, &s1v, &c1v);
    float tc = 2.f * c1v;
    float sp = 0.f, cp = 1.f;       // sin(0), cos(0)
    float sc = s1v, cc = c1v;       // sin(x), cos(x)
    float radv[8], dcov[8];
    #pragma unroll
    for (int n = 0; n < 8; n++) {
        float kn = (float)(n + 1) * KPI;
        float rad = A * sc * inv;
        radv[n] = rad;
        dcov[n] = (A * kn * cc - rad) * inv;
        float sn2 = tc * sc - sp; sp = sc; sc = sn2;
        float cn2 = tc * cc - cp; cp = cc; cc = cn2;
    }
    *reinterpret_cast<float4*>(g_radial + e*8)      = make_float4(radv[0], radv[1], radv[2], radv[3]);
    *reinterpret_cast<float4*>(g_radial + e*8 + 4)  = make_float4(radv[4], radv[5], radv[6], radv[7]);
    *reinterpret_cast<float4*>(g_dradial + e*8)     = make_float4(dcov[0], dcov[1], dcov[2], dcov[3]);
    *reinterpret_cast<float4*>(g_dradial + e*8 + 4) = make_float4(dcov[4], dcov[5], dcov[6], dcov[7]);
    atomicAdd(&g_icsr[rw], 1);
    atomicAdd(&g_icsr[NN + cl], 1);
}

// ---------------- CSR: exclusive scans for both R and C in one launch ----------------
__global__ void k_scan2() {
    __shared__ int part[1024];
    const int CH = 32;
    int t = threadIdx.x;
    int base = t * CH;
    for (int pass = 0; pass < 2; pass++) {
        const int* cnt = pass ? (g_icsr + NN) : g_icsr;
        int*       off = pass ? g_offC : g_offR;
        int s = 0;
        for (int i = 0; i < CH; i++) {
            int idx = base + i;
            if (idx < NN) s += cnt[idx];
        }
        part[t] = s;
        __syncthreads();
        for (int o = 1; o < 1024; o <<= 1) {
            int v = (t >= o) ? part[t - o] : 0;
            __syncthreads();
            part[t] += v;
            __syncthreads();
        }
        int run = (t > 0) ? part[t - 1] : 0;
        for (int i = 0; i < CH; i++) {
            int idx = base + i;
            if (idx < NN) { off[idx] = run; run += cnt[idx]; }
        }
        __syncthreads();
    }
}

// ---------------- CSR: fill (unordered) ----------------
__global__ void k_fill(const int* __restrict__ ei) {
    int e = blockIdx.x * blockDim.x + threadIdx.x;
    if (e >= NE) return;
    int rw = ei[e], cl = ei[NE + e];
    int p1 = g_offR[rw] + atomicAdd(&g_icsr[2*NN + rw], 1);
    g_lstR[p1] = e;
    int p2 = g_offC[cl] + atomicAdd(&g_icsr[3*NN + cl], 1);
    g_lstC[p2] = e;
}

// ---------------- CSR: sort buckets ascending (R and C split across threads) ----
__global__ void k_sort2() {
    int t = blockIdx.x * blockDim.x + threadIdx.x;
    if (t >= 2 * NN) return;
    int n = (t < NN) ? t : t - NN;
    int* lst = (t < NN) ? g_lstR : g_lstC;
    int lo  = (t < NN) ? g_offR[n] : g_offC[n];
    int hi  = lo + ((t < NN) ? g_icsr[n] : g_icsr[NN + n]);
    for (int i = lo + 1; i < hi; i++) {
        int key = lst[i], j = i - 1;
        while (j >= lo && lst[j] > key) { lst[j+1] = lst[j]; j--; }
        lst[j+1] = key;
    }
}

// ---------------- forward: h0 init = emb[z] @ W_init ----------------
__global__ void k_node_init(const float* __restrict__ emb, const int* __restrict__ z,
                            const float* __restrict__ W_init) {
    __shared__ float Ws[256];
    for (int i = threadIdx.x; i < 256; i += blockDim.x) Ws[i] = W_init[i];
    __syncthreads();
    int t = blockIdx.x * blockDim.x + threadIdx.x;
    if (t >= NN * 16) return;
    int n = t >> 4, d = t & 15;
    const float* er = emb + z[n] * 16;
    float acc = 0.f;
    #pragma unroll
    for (int k = 0; k < 16; k++) acc += er[k] * Ws[k*16 + d];
    g_h00[t] = acc;
}

// ---------------- forward: block0 gather + fused node update ----------------
__global__ void k_gath_fwd0(const int* __restrict__ ei,
                            const float* __restrict__ Wr, const float* __restrict__ br,
                            const float* __restrict__ Wout) {
    __shared__ float Wrs[640], brs[80], W0s[256], W1s[256], W2s[256];
    for (int i = threadIdx.x; i < 640; i += blockDim.x) Wrs[i] = Wr[i];
    for (int i = threadIdx.x; i < 80;  i += blockDim.x) brs[i] = br[i];
    for (int i = threadIdx.x; i < 256; i += blockDim.x) {
        W0s[i] = Wout[i]; W1s[i] = Wout[256 + i]; W2s[i] = Wout[512 + i];
    }
    __syncthreads();
    int t = blockIdx.x * blockDim.x + threadIdx.x;
    int n = t >> 4, c = t & 15;
    float w0b = brs[c], w1b = brs[16 + c], w2b = brs[32 + c];
    float acc0 = 0.f, a1[3] = {0,0,0}, a2[5] = {0,0,0,0,0};
    int lo = g_offR[n], hi = lo + g_icsr[n];
    for (int i = lo; i < hi; i++) {
        int e = g_lstR[i];
        int cl = ei[NE + e];
        float4 g = g_geo[e];
        float s1[3], s2[5];
        sh_basis_f(g.x, g.y, g.z, s1, s2);
        float4 r0 = *reinterpret_cast<const float4*>(g_radial + e*8);
        float4 r1 = *reinterpret_cast<const float4*>(g_radial + e*8 + 4);
        float rad[8] = {r0.x, r0.y, r0.z, r0.w, r1.x, r1.y, r1.z, r1.w};
        float w0 = w0b, w1 = w1b, w2 = w2b;
        #pragma unroll
        for (int k = 0; k < 8; k++) {
            w0 += rad[k] * Wrs[k*80 + c];
            w1 += rad[k] * Wrs[k*80 + 16 + c];
            w2 += rad[k] * Wrs[k*80 + 32 + c];
        }
        float h0c = g_h00[cl*16 + c];
        acc0 += w0 * h0c;
        float f1 = w1 * h0c, f2 = w2 * h0c;
        #pragma unroll
        for (int m = 0; m < 3; m++) a1[m] += f1 * s1[m];
        #pragma unroll
        for (int m = 0; m < 5; m++) a2[m] += f2 * s2[m];
    }
    // fused node update (convergent): lane c plays output channel d=c
    float h01v = g_h00[n*16 + c];
    float h11v[3] = {0,0,0}, h21v[5] = {0,0,0,0,0};
    #pragma unroll
    for (int cc = 0; cc < 16; cc++) {
        float b0 = SHFL16(acc0, cc);
        h01v += b0 * W0s[cc*16 + c];
        float w1 = W1s[cc*16 + c];
        #pragma unroll
        for (int m = 0; m < 3; m++) h11v[m] += SHFL16(a1[m], cc) * w1;
        float w2 = W2s[cc*16 + c];
        #pragma unroll
        for (int m = 0; m < 5; m++) h21v[m] += SHFL16(a2[m], cc) * w2;
    }
    g_h01[n*16 + c] = h01v;
    #pragma unroll
    for (int m = 0; m < 3; m++) g_h11[n*48 + c*3 + m] = h11v[m];
    #pragma unroll
    for (int m = 0; m < 5; m++) g_h21[n*80 + c*5 + m] = h21v[m];
}

// ---------------- forward: block1 gather + fused readout + bwd_node1 ----------------
__global__ void k_fwd1_readout(const int* __restrict__ ei,
                               const float* __restrict__ Wr, const float* __restrict__ br,
                               const float* __restrict__ W10, const float* __restrict__ W_read,
                               const float* __restrict__ W1, const float* __restrict__ b1,
                               const float* __restrict__ W2, const float* __restrict__ b2) {
    __shared__ float Wrs[640], brs[80], W10s[256], WRs[256], W1s[256], W2s[16], b1s[16];
    __shared__ float b2s;
    __shared__ double esum[16];
    for (int i = threadIdx.x; i < 640; i += blockDim.x) Wrs[i] = Wr[i];
    for (int i = threadIdx.x; i < 80;  i += blockDim.x) brs[i] = br[i];
    for (int i = threadIdx.x; i < 256; i += blockDim.x) {
        W10s[i] = W10[i]; WRs[i] = W_read[i]; W1s[i] = W1[i];
    }
    if (threadIdx.x < 16) { W2s[threadIdx.x] = W2[threadIdx.x]; b1s[threadIdx.x] = b1[threadIdx.x]; }
    if (threadIdx.x == 0) b2s = b2[0];
    __syncthreads();
    int t = blockIdx.x * blockDim.x + threadIdx.x;
    int n = t >> 4, c = t & 15;
    float w0b = brs[c], w3b = brs[48 + c], w4b = brs[64 + c];
    float acc = 0.f;                       // a01[n,c]
    int lo = g_offR[n], hi = lo + g_icsr[n];
    for (int i = lo; i < hi; i++) {
        int e = g_lstR[i];
        int cl = ei[NE + e];
        float4 g = g_geo[e];
        float s1[3], s2[5];
        sh_basis_f(g.x, g.y, g.z, s1, s2);
        float4 r0 = *reinterpret_cast<const float4*>(g_radial + e*8);
        float4 r1 = *reinterpret_cast<const float4*>(g_radial + e*8 + 4);
        float rad[8] = {r0.x, r0.y, r0.z, r0.w, r1.x, r1.y, r1.z, r1.w};
        float w0 = w0b, w3 = w3b, w4 = w4b;
        #pragma unroll
        for (int k = 0; k < 8; k++) {
            w0 += rad[k] * Wrs[k*80 + c];
            w3 += rad[k] * Wrs[k*80 + 48 + c];
            w4 += rad[k] * Wrs[k*80 + 64 + c];
        }
        float h0c = g_h01[cl*16 + c];
        float d1 = 0.f, d2 = 0.f;
        #pragma unroll
        for (int m = 0; m < 3; m++) d1 += g_h11[cl*48 + c*3 + m] * s1[m];
        #pragma unroll
        for (int m = 0; m < 5; m++) d2 += g_h21[cl*80 + c*5 + m] * s2[m];
        acc += w0 * h0c + w3 * d1 + w4 * d2;
    }
    // distributed readout (convergent; lane c == channel index)
    float h0f = g_h01[n*16 + c];
    #pragma unroll
    for (int cc = 0; cc < 16; cc++) h0f += SHFL16(acc, cc) * W10s[cc*16 + c];
    float invv = 0.f;
    #pragma unroll
    for (int cc = 0; cc < 16; cc++) invv += SHFL16(h0f, cc) * WRs[cc*16 + c];
    float tt = b1s[c];
    #pragma unroll
    for (int d = 0; d < 16; d++) tt += SHFL16(invv, d) * W1s[d*16 + c];
    float sg = 1.f / (1.f + expf(-tt));
    float sl = tt * sg * W2s[c];
    float sp = sg * (1.f + tt * (1.f - sg)) * W2s[c];
    float q = 0.f;
    #pragma unroll
    for (int k = 0; k < 16; k++) q += SHFL16(sp, k) * W1s[c*16 + k];
    float g0f = 0.f;
    #pragma unroll
    for (int d = 0; d < 16; d++) g0f += SHFL16(q, d) * WRs[c*16 + d];
    g_g0f[n*16 + c] = g0f;
    float ga = 0.f;
    #pragma unroll
    for (int d = 0; d < 16; d++) ga += SHFL16(g0f, d) * W10s[c*16 + d];
    g_ga01[n*16 + c] = ga;
    // energy
    #pragma unroll
    for (int off = 8; off > 0; off >>= 1) sl += __shfl_xor_sync(0xffffffffu, sl, off, 16);
    int grp = threadIdx.x >> 4;
    if (c == 0) esum[grp] = (double)(sl + b2s);
    __syncthreads();
    if (threadIdx.x == 0) {
        double s = 0.0;
        #pragma unroll
        for (int i = 0; i < 16; i++) s += esum[i];
        atomicAdd(&g_energy, s);
    }
}

// ---------------- backward: block1 slim gather + fused bwd_node0 ----------------
__global__ void k_gath_bwd1(const int* __restrict__ ei,
                            const float* __restrict__ Wr, const float* __restrict__ br,
                            const float* __restrict__ Wout) {
    __shared__ float Wrs[640], brs[80], W0s[256], W1s[256], W2s[256];
    for (int i = threadIdx.x; i < 640; i += blockDim.x) Wrs[i] = Wr[i];
    for (int i = threadIdx.x; i < 80;  i += blockDim.x) brs[i] = br[i];
    for (int i = threadIdx.x; i < 256; i += blockDim.x) {
        W0s[i] = Wout[i]; W1s[i] = Wout[256 + i]; W2s[i] = Wout[512 + i];
    }
    __syncthreads();
    int t = blockIdx.x * blockDim.x + threadIdx.x;
    int n = t >> 4, c = t & 15;
    float w0b = brs[c], w3b = brs[48 + c], w4b = brs[64 + c];
    float g01acc = g_g0f[n*16 + c];           // identity path
    float g11acc[3] = {0,0,0}, g21acc[5] = {0,0,0,0,0};
    int lo = g_offC[n], hi = lo + g_icsr[NN + n];
    for (int i = lo; i < hi; i++) {
        int e = g_lstC[i];
        int rw = ei[e];
        float4 g = g_geo[e];
        float s1[3], s2[5];
        sh_basis_f(g.x, g.y, g.z, s1, s2);
        float4 r0 = *reinterpret_cast<const float4*>(g_radial + e*8);
        float4 r1 = *reinterpret_cast<const float4*>(g_radial + e*8 + 4);
        float rad[8] = {r0.x, r0.y, r0.z, r0.w, r1.x, r1.y, r1.z, r1.w};
        float w0 = w0b, w3 = w3b, w4 = w4b;
        #pragma unroll
        for (int k = 0; k < 8; k++) {
            w0 += rad[k] * Wrs[k*80 + c];
            w3 += rad[k] * Wrs[k*80 + 48 + c];
            w4 += rad[k] * Wrs[k*80 + 64 + c];
        }
        float gm0 = g_ga01[rw*16 + c];
        g01acc += gm0 * w0;
        float gw3 = gm0 * w3, gw4 = gm0 * w4;
        #pragma unroll
        for (int m = 0; m < 3; m++) g11acc[m] += gw3 * s1[m];
        #pragma unroll
        for (int m = 0; m < 5; m++) g21acc[m] += gw4 * s2[m];
    }
    // fused bwd_node0 (convergent; lane c == output channel)
    float ga00 = 0.f, ga10[3] = {0,0,0}, ga20[5] = {0,0,0,0,0};
    #pragma unroll
    for (int d = 0; d < 16; d++) {
        ga00 += SHFL16(g01acc, d) * W0s[c*16 + d];
        float w1 = W1s[c*16 + d];
        #pragma unroll
        for (int m = 0; m < 3; m++) ga10[m] += SHFL16(g11acc[m], d) * w1;
        float w2 = W2s[c*16 + d];
        #pragma unroll
        for (int m = 0; m < 5; m++) ga20[m] += SHFL16(g21acc[m], d) * w2;
    }
    g_ga00[n*16 + c] = ga00;
    #pragma unroll
    for (int m = 0; m < 3; m++) g_ga10[n*48 + c*3 + m] = ga10[m];
    #pragma unroll
    for (int m = 0; m < 5; m++) g_ga20[n*80 + c*5 + m] = ga20[m];
}

// ---------------- backward: BOTH blocks, per-lane gv partials, 3-value butterfly ----
__global__ void k_bwd_edge_all(const int* __restrict__ ei,
                               const float* __restrict__ Wr, const float* __restrict__ br) {
    // Wr layout: block0 at [0,640), block1 at [640,1280); br: [0,80) and [80,160)
    __shared__ float Wrs[1280], brs[160];
    for (int i = threadIdx.x; i < 1280; i += blockDim.x) Wrs[i] = Wr[i];
    for (int i = threadIdx.x; i < 160;  i += blockDim.x) brs[i] = br[i];
    __syncthreads();
    long t = (long)blockIdx.x * blockDim.x + threadIdx.x;
    int e = (int)(t >> 4), c = (int)(t & 15);
    int rw = ei[e], cl = ei[NE + e];
    float4 g = g_geo[e];
    float s1[3], s2[5];
    sh_basis_f(g.x, g.y, g.z, s1, s2);
    float4 r0 = *reinterpret_cast<const float4*>(g_radial + e*8);
    float4 r1 = *reinterpret_cast<const float4*>(g_radial + e*8 + 4);
    float rad[8] = {r0.x, r0.y, r0.z, r0.w, r1.x, r1.y, r1.z, r1.w};
    float4 d0 = *reinterpret_cast<const float4*>(g_dradial + e*8);
    float4 dd1 = *reinterpret_cast<const float4*>(g_dradial + e*8 + 4);
    float dco[8] = {d0.x, d0.y, d0.z, d0.w, dd1.x, dd1.y, dd1.z, dd1.w};

    float b0w1 = brs[16 + c], b0w2 = brs[32 + c];
    float b1w3 = brs[128 + c], b1w4 = brs[144 + c];
    float D0w0 = 0.f, D0w1 = 0.f, D0w2 = 0.f, D1w0 = 0.f, D1w3 = 0.f, D1w4 = 0.f;
    #pragma unroll
    for (int n = 0; n < 8; n++) {
        float rr = rad[n], dd = dco[n];
        b0w1 += rr * Wrs[n*80 + 16 + c];
        b0w2 += rr * Wrs[n*80 + 32 + c];
        b1w3 += rr * Wrs[640 + n*80 + 48 + c];
        b1w4 += rr * Wrs[640 + n*80 + 64 + c];
        D0w0 += dd * Wrs[n*80 + c];
        D0w1 += dd * Wrs[n*80 + 16 + c];
        D0w2 += dd * Wrs[n*80 + 32 + c];
        D1w0 += dd * Wrs[640 + n*80 + c];
        D1w3 += dd * Wrs[640 + n*80 + 48 + c];
        D1w4 += dd * Wrs[640 + n*80 + 64 + c];
    }

    float g1[3], g2[5], grp;
    {
        float gm0 = g_ga01[rw*16 + c];
        float h0c = g_h01[cl*16 + c];
        float h1c[3], h2c[5];
        #pragma unroll
        for (int m = 0; m < 3; m++) h1c[m] = g_h11[cl*48 + c*3 + m];
        #pragma unroll
        for (int m = 0; m < 5; m++) h2c[m] = g_h21[cl*80 + c*5 + m];
        float gw3 = gm0 * b1w3, gw4 = gm0 * b1w4;
        #pragma unroll
        for (int m = 0; m < 3; m++) g1[m] = gw3 * h1c[m];
        #pragma unroll
        for (int m = 0; m < 5; m++) g2[m] = gw4 * h2c[m];
        float d1 = 0.f, d2 = 0.f;
        #pragma unroll
        for (int m = 0; m < 3; m++) d1 += h1c[m] * s1[m];
        #pragma unroll
        for (int m = 0; m < 5; m++) d2 += h2c[m] * s2[m];
        grp = (gm0 * h0c) * D1w0 + (gm0 * d1) * D1w3 + (gm0 * d2) * D1w4;
    }
    {
        float gm0 = g_ga00[rw*16 + c];
        float gm1[3], gm2[5];
        #pragma unroll
        for (int m = 0; m < 3; m++) gm1[m] = g_ga10[rw*48 + c*3 + m];
        #pragma unroll
        for (int m = 0; m < 5; m++) gm2[m] = g_ga20[rw*80 + c*5 + m];
        float h0c = g_h00[cl*16 + c];
        float d1 = 0.f, d2 = 0.f;
        #pragma unroll
        for (int m = 0; m < 3; m++) d1 += gm1[m] * s1[m];
        #pragma unroll
        for (int m = 0; m < 5; m++) d2 += gm2[m] * s2[m];
        float w1h = b0w1 * h0c, w2h = b0w2 * h0c;
        #pragma unroll
        for (int m = 0; m < 3; m++) g1[m] += gm1[m] * w1h;
        #pragma unroll
        for (int m = 0; m < 5; m++) g2[m] += gm2[m] * w2h;
        grp += (gm0 * h0c) * D0w0 + (h0c * d1) * D0w1 + (h0c * d2) * D0w2;
    }

    float ux = g.x, uy = g.y, uz = g.z, invr = 1.f / g.w;
    const float SQ3 = 1.7320508075688772f;
    const float S15 = 3.872983346207417f;
    const float S5  = 2.23606797749979f;
    float gux = SQ3 * g1[0] + S15 * (uy * g2[0] + uz * g2[3] + ux * g2[4]);
    float guy = SQ3 * g1[1] + S15 * (ux * g2[0] + uz * g2[1] - uy * g2[4]);
    float guz = SQ3 * g1[2] + S15 * (uy * g2[1] + ux * g2[3]) + 3.f * S5 * uz * g2[2];
    float guu = gux * ux + guy * uy + guz * uz;
    float gvx = grp * ux + (gux - guu * ux) * invr;
    float gvy = grp * uy + (guy - guu * uy) * invr;
    float gvz = grp * uz + (guz - guu * uz) * invr;

    #pragma unroll
    for (int off = 8; off > 0; off >>= 1) {
        gvx += __shfl_xor_sync(0xffffffffu, gvx, off, 16);
        gvy += __shfl_xor_sync(0xffffffffu, gvy, off, 16);
        gvz += __shfl_xor_sync(0xffffffffu, gvz, off, 16);
    }
    if (c == 0) {
        g_gv[e*3 + 0] = gvx;
        g_gv[e*3 + 1] = gvy;
        g_gv[e*3 + 2] = gvz;
    }
}

// ---------------- forces: 8 lanes/node, sums bit-identical to XLA order ----------------
__global__ void k_forces(float* __restrict__ out) {
    int t = blockIdx.x * blockDim.x + threadIdx.x;
    if (t >= NN * 8) return;
    int n = t >> 3, l = t & 7;
    if (t == 0) out[0] = (float)g_energy;
    float acc = 0.f;
    if (l < 3) {
        int lo = g_offR[n], hi = lo + g_icsr[n];
        for (int i = lo; i < hi; i++) acc += g_gv[g_lstR[i]*3 + l];
    } else if (l < 7 && l >= 4) {
        int m = l - 4;
        int lo = g_offC[n], hi = lo + g_icsr[NN + n];
        for (int i = lo; i < hi; i++) acc += -g_gv[g_lstC[i]*3 + m];
    }
    float partner = __shfl_down_sync(0xffffffffu, acc, 4, 8);
    if (l < 3) out[1 + n*3 + l] = -(acc + partner);
}

// ---------------- host ----------------
extern "C" void kernel_launch(void* const* d_in, const int* in_sizes, int n_in,
                              void* d_out, int out_size) {
    const float* pos    = (const float*)d_in[0];
    const int*   z      = (const int*)  d_in[1];
    const int*   ei     = (const int*)  d_in[2];
    const float* emb    = (const float*)d_in[3];
    const float* W_init = (const float*)d_in[4];
    const float* Wr     = (const float*)d_in[5];
    const float* br     = (const float*)d_in[6];
    const float* W_out  = (const float*)d_in[7];
    const float* W_read = (const float*)d_in[8];
    const float* W1     = (const float*)d_in[9];
    const float* b1     = (const float*)d_in[10];
    const float* W2     = (const float*)d_in[11];
    const float* b2     = (const float*)d_in[12];
    float* out = (float*)d_out;

    void *pen, *picsr;
    cudaGetSymbolAddress(&pen,   g_energy);
    cudaGetSymbolAddress(&picsr, g_icsr);

    cudaMemsetAsync(pen,   0, sizeof(double), 0);
    cudaMemsetAsync(picsr, 0, sizeof(int) * 4 * NN, 0);

    const int TPB = 256;
    k_geom_fwd    <<<NE / TPB, TPB>>>(pos, ei);
    k_scan2       <<<1, 1024>>>();
    k_fill        <<<NE / TPB, TPB>>>(ei);
    k_sort2       <<<(2 * NN + TPB - 1) / TPB, TPB>>>();
    k_node_init   <<<NN * 16 / TPB, TPB>>>(emb, z, W_init);
    k_gath_fwd0   <<<NN * 16 / TPB, TPB>>>(ei, Wr, br, W_out);
    k_fwd1_readout<<<NN * 16 / TPB, TPB>>>(ei, Wr + 640, br + 80,
                                           W_out + 768, W_read, W1, b1, W2, b2);
    k_gath_bwd1   <<<NN * 16 / TPB, TPB>>>(ei, Wr + 640, br + 80, W_out);
    k_bwd_edge_all<<<NE * 16 / TPB, TPB>>>(ei, Wr, br);
    k_forces      <<<(NN * 8 + TPB - 1) / TPB, TPB>>>(out);
}